// round 3
// baseline (speedup 1.0000x reference)
#include <cuda_runtime.h>
#include <cstdint>

#define BATCH 16384
#define D     1024
#define LN_EPS 1e-5f

// ---------------- scratch (static device globals; no runtime alloc) ----------
__device__ float g_fast[(size_t)BATCH * D];        // 64 MB: fast = x @ W_fast^T
__device__ float g_part[(size_t)8 * D * D];        // 32 MB: split-K partials of fast^T @ x
__device__ float g_msq_part[64 * D];               // per-row-block partial sums of fast^2
__device__ float g_msq[D];                         // mean(fast^2) per output column
__device__ float g_efflr[1];                       // mean(plasticity) * 0.1

// ---------------- helpers ----------------------------------------------------
__device__ __forceinline__ unsigned tf32u(float x) {
    unsigned r;
    asm("cvt.rna.tf32.f32 %0, %1;" : "=r"(r) : "f"(x));
    return r;
}
__device__ __forceinline__ unsigned fu(float x) { return __float_as_uint(x); }

__device__ __forceinline__ void mma8(float c[4],
                                     unsigned a0, unsigned a1, unsigned a2, unsigned a3,
                                     unsigned b0, unsigned b1) {
    asm volatile(
        "mma.sync.aligned.m16n8k8.row.col.f32.tf32.tf32.f32 "
        "{%0,%1,%2,%3}, {%4,%5,%6,%7}, {%8,%9}, {%0,%1,%2,%3};\n"
        : "+f"(c[0]), "+f"(c[1]), "+f"(c[2]), "+f"(c[3])
        : "r"(a0), "r"(a1), "r"(a2), "r"(a3), "r"(b0), "r"(b1));
}

__device__ __forceinline__ float warpSum(float v) {
    #pragma unroll
    for (int o = 16; o > 0; o >>= 1) v += __shfl_xor_sync(0xffffffffu, v, o);
    return v;
}

// ============================================================================
// GEMM 1: C[m][n] = sum_k A[m][k] * W[n][k]   (both K-major; M=16384/..., N=K=1024)
// 128x128 tile, BK=16, 8 warps (2x4), warp tile 64x32, m16n8k8 tf32.
// If C == nullptr, writes to g_fast.
// ============================================================================
__global__ __launch_bounds__(256, 1)
void gemm_xw(const float* __restrict__ A, const float* __restrict__ W, float* C) {
    const int K = D, N = D;
    __shared__ float As[128][20];   // [m][k], pad 20 -> conflict-free frag loads
    __shared__ float Bs[128][20];   // [n][k]

    float* Cout = C ? C : (float*)g_fast;

    const int tid  = threadIdx.x;
    const int warp = tid >> 5, lane = tid & 31;
    const int g = lane >> 2, tg = lane & 3;
    const int wm = (warp >> 2) * 64;   // 0 / 64
    const int wn = (warp & 3) * 32;    // 0..96

    const float* Ab = A + (size_t)blockIdx.y * 128 * K;
    const float* Wb = W + (size_t)blockIdx.x * 128 * K;

    float acc[4][4][4];
    #pragma unroll
    for (int i = 0; i < 4; i++)
        #pragma unroll
        for (int j = 0; j < 4; j++)
            #pragma unroll
            for (int q = 0; q < 4; q++) acc[i][j][q] = 0.f;

    const int lrow = tid >> 2;          // 0..63
    const int lkq  = (tid & 3) << 2;    // 0,4,8,12

    for (int k0 = 0; k0 < K; k0 += 16) {
        #pragma unroll
        for (int i = 0; i < 2; i++) {
            int row = lrow + i * 64;
            float4 va = *(const float4*)(Ab + (size_t)row * K + k0 + lkq);
            float4 vb = *(const float4*)(Wb + (size_t)row * K + k0 + lkq);
            va.x = __uint_as_float(tf32u(va.x)); va.y = __uint_as_float(tf32u(va.y));
            va.z = __uint_as_float(tf32u(va.z)); va.w = __uint_as_float(tf32u(va.w));
            vb.x = __uint_as_float(tf32u(vb.x)); vb.y = __uint_as_float(tf32u(vb.y));
            vb.z = __uint_as_float(tf32u(vb.z)); vb.w = __uint_as_float(tf32u(vb.w));
            *(float4*)&As[row][lkq] = va;
            *(float4*)&Bs[row][lkq] = vb;
        }
        __syncthreads();

        #pragma unroll
        for (int ks = 0; ks < 2; ks++) {
            const int kk = ks * 8;
            unsigned a[4][4], b[4][2];
            #pragma unroll
            for (int im = 0; im < 4; im++) {
                int m = wm + im * 16;
                a[im][0] = fu(As[m + g    ][kk + tg    ]);
                a[im][1] = fu(As[m + g + 8][kk + tg    ]);
                a[im][2] = fu(As[m + g    ][kk + tg + 4]);
                a[im][3] = fu(As[m + g + 8][kk + tg + 4]);
            }
            #pragma unroll
            for (int jn = 0; jn < 4; jn++) {
                int n = wn + jn * 8;
                b[jn][0] = fu(Bs[n + g][kk + tg    ]);
                b[jn][1] = fu(Bs[n + g][kk + tg + 4]);
            }
            #pragma unroll
            for (int im = 0; im < 4; im++)
                #pragma unroll
                for (int jn = 0; jn < 4; jn++)
                    mma8(acc[im][jn], a[im][0], a[im][1], a[im][2], a[im][3],
                         b[jn][0], b[jn][1]);
        }
        __syncthreads();
    }

    #pragma unroll
    for (int im = 0; im < 4; im++) {
        int m = blockIdx.y * 128 + wm + im * 16 + g;
        #pragma unroll
        for (int jn = 0; jn < 4; jn++) {
            int n = blockIdx.x * 128 + wn + jn * 8 + tg * 2;
            *(float2*)(Cout + (size_t)m * N + n)       = make_float2(acc[im][jn][0], acc[im][jn][1]);
            *(float2*)(Cout + (size_t)(m + 8) * N + n) = make_float2(acc[im][jn][2], acc[im][jn][3]);
        }
    }
}

// ============================================================================
// GEMM 2 (split-K): partial[z][m][n] = sum_{k in z-chunk} fast[k][m] * x[k][n]
// grid (8 ntiles, 8 mtiles, 8 splits); each block owns its partial region.
// ============================================================================
__global__ __launch_bounds__(256, 1)
void gemm_atb(const float* __restrict__ X) {
    __shared__ float As[16][136];   // [k][m], pad 136 -> conflict-free
    __shared__ float Bs[16][136];   // [k][n]

    const int tid  = threadIdx.x;
    const int warp = tid >> 5, lane = tid & 31;
    const int g = lane >> 2, tg = lane & 3;
    const int wm = (warp >> 2) * 64;
    const int wn = (warp & 3) * 32;
    const int m0 = blockIdx.y * 128, n0 = blockIdx.x * 128;
    const int kbase = blockIdx.z * 2048;

    float acc[4][4][4];
    #pragma unroll
    for (int i = 0; i < 4; i++)
        #pragma unroll
        for (int j = 0; j < 4; j++)
            #pragma unroll
            for (int q = 0; q < 4; q++) acc[i][j][q] = 0.f;

    const int lk  = tid >> 5;          // 0..7
    const int lmq = (tid & 31) << 2;   // 0..124

    for (int k0 = kbase; k0 < kbase + 2048; k0 += 16) {
        #pragma unroll
        for (int i = 0; i < 2; i++) {
            int kr = lk + i * 8;
            float4 va = *(const float4*)(g_fast + (size_t)(k0 + kr) * D + m0 + lmq);
            float4 vb = *(const float4*)(X      + (size_t)(k0 + kr) * D + n0 + lmq);
            va.x = __uint_as_float(tf32u(va.x)); va.y = __uint_as_float(tf32u(va.y));
            va.z = __uint_as_float(tf32u(va.z)); va.w = __uint_as_float(tf32u(va.w));
            vb.x = __uint_as_float(tf32u(vb.x)); vb.y = __uint_as_float(tf32u(vb.y));
            vb.z = __uint_as_float(tf32u(vb.z)); vb.w = __uint_as_float(tf32u(vb.w));
            *(float4*)&As[kr][lmq] = va;
            *(float4*)&Bs[kr][lmq] = vb;
        }
        __syncthreads();

        #pragma unroll
        for (int ks = 0; ks < 2; ks++) {
            const int kk = ks * 8;
            unsigned a[4][4], b[4][2];
            #pragma unroll
            for (int im = 0; im < 4; im++) {
                int m = wm + im * 16;
                a[im][0] = fu(As[kk + tg    ][m + g    ]);
                a[im][1] = fu(As[kk + tg    ][m + g + 8]);
                a[im][2] = fu(As[kk + tg + 4][m + g    ]);
                a[im][3] = fu(As[kk + tg + 4][m + g + 8]);
            }
            #pragma unroll
            for (int jn = 0; jn < 4; jn++) {
                int n = wn + jn * 8;
                b[jn][0] = fu(Bs[kk + tg    ][n + g]);
                b[jn][1] = fu(Bs[kk + tg + 4][n + g]);
            }
            #pragma unroll
            for (int im = 0; im < 4; im++)
                #pragma unroll
                for (int jn = 0; jn < 4; jn++)
                    mma8(acc[im][jn], a[im][0], a[im][1], a[im][2], a[im][3],
                         b[jn][0], b[jn][1]);
        }
        __syncthreads();
    }

    float* Cp = g_part + (size_t)blockIdx.z * D * D;
    #pragma unroll
    for (int im = 0; im < 4; im++) {
        int m = m0 + wm + im * 16 + g;
        #pragma unroll
        for (int jn = 0; jn < 4; jn++) {
            int n = n0 + wn + jn * 8 + tg * 2;
            *(float2*)(Cp + (size_t)m * D + n)       = make_float2(acc[im][jn][0], acc[im][jn][1]);
            *(float2*)(Cp + (size_t)(m + 8) * D + n) = make_float2(acc[im][jn][2], acc[im][jn][3]);
        }
    }
}

// ============================================================================
// mean(fast^2, axis=0): two deterministic stages
// ============================================================================
__global__ void msq_stageA() {
    int c  = blockIdx.x * 256 + threadIdx.x;     // grid.x = 4
    int r0 = blockIdx.y * 256;                   // grid.y = 64
    float s0 = 0.f, s1 = 0.f, s2 = 0.f, s3 = 0.f;
    const float* fp = g_fast + (size_t)r0 * D + c;
    #pragma unroll 4
    for (int j = 0; j < 256; j += 4) {
        float v0 = fp[(size_t)(j + 0) * D];
        float v1 = fp[(size_t)(j + 1) * D];
        float v2 = fp[(size_t)(j + 2) * D];
        float v3 = fp[(size_t)(j + 3) * D];
        s0 += v0 * v0; s1 += v1 * v1; s2 += v2 * v2; s3 += v3 * v3;
    }
    g_msq_part[blockIdx.y * D + c] = (s0 + s1) + (s2 + s3);
}

__global__ void msq_stageB() {
    int c = blockIdx.x * 256 + threadIdx.x;      // grid.x = 4
    float s = 0.f;
    #pragma unroll
    for (int j = 0; j < 64; j++) s += g_msq_part[j * D + c];
    g_msq[c] = s * (1.0f / (float)BATCH);
}

// ============================================================================
// eff_lr = mean(plasticity) * 0.1
// ============================================================================
__global__ void efflr_kernel(const float* __restrict__ p) {
    int t = threadIdx.x;
    float s = 0.f;
    for (int j = t; j < BATCH; j += 256) s += p[j];
    s = warpSum(s);
    __shared__ float sh[8];
    if ((t & 31) == 0) sh[t >> 5] = s;
    __syncthreads();
    if (t == 0) {
        float tot = 0.f;
        #pragma unroll
        for (int i = 0; i < 8; i++) tot += sh[i];
        g_efflr[0] = tot * (0.1f / (float)BATCH);
    }
}

// ============================================================================
// W_fast_new = W_fast + tanh(hebb - msq[o]*W_fast) * eff_lr
// one block per output row o
// ============================================================================
__global__ __launch_bounds__(256)
void finalize_w(const float* __restrict__ Wf, float* __restrict__ wnew) {
    int o = blockIdx.x;
    float msq = g_msq[o];
    float lr  = g_efflr[0];
    for (int j = threadIdx.x; j < D; j += 256) {
        size_t i = (size_t)o * D + j;
        float h = 0.f;
        #pragma unroll
        for (int s = 0; s < 8; s++) h += g_part[(size_t)s * D * D + i];
        float wf = Wf[i];
        wnew[i] = wf + tanhf(h * (1.0f / (float)BATCH) - msq * wf) * lr;
    }
}

// ============================================================================
// LayerNorm over combined = slow + alpha*fast; one block per row
// ============================================================================
__global__ __launch_bounds__(256)
void ln_kernel(const float* __restrict__ slow, const float* __restrict__ alpha,
               const float* __restrict__ gamma, const float* __restrict__ beta,
               float* __restrict__ out) {
    int r = blockIdx.x, t = threadIdx.x;
    const float a = alpha[0];
    float4 s4 = ((const float4*)(slow   + (size_t)r * D))[t];
    float4 f4 = ((const float4*)(g_fast + (size_t)r * D))[t];
    float4 v;
    v.x = s4.x + a * f4.x; v.y = s4.y + a * f4.y;
    v.z = s4.z + a * f4.z; v.w = s4.w + a * f4.w;

    float sum = (v.x + v.y) + (v.z + v.w);
    float sq  = (v.x * v.x + v.y * v.y) + (v.z * v.z + v.w * v.w);
    sum = warpSum(sum); sq = warpSum(sq);

    __shared__ float sh[16];
    int w = t >> 5, l = t & 31;
    if (l == 0) { sh[w] = sum; sh[8 + w] = sq; }
    __syncthreads();
    if (t == 0) {
        float s = 0.f, q = 0.f;
        #pragma unroll
        for (int i = 0; i < 8; i++) { s += sh[i]; q += sh[8 + i]; }
        sh[0] = s; sh[8] = q;
    }
    __syncthreads();
    float mu  = sh[0] * (1.0f / (float)D);
    float var = sh[8] * (1.0f / (float)D) - mu * mu;
    float rs  = rsqrtf(var + LN_EPS);

    float4 g4 = ((const float4*)gamma)[t];
    float4 b4 = ((const float4*)beta)[t];
    float4 o4;
    o4.x = (v.x - mu) * rs * g4.x + b4.x;
    o4.y = (v.y - mu) * rs * g4.y + b4.y;
    o4.z = (v.z - mu) * rs * g4.z + b4.z;
    o4.w = (v.w - mu) * rs * g4.w + b4.w;
    ((float4*)(out + (size_t)r * D))[t] = o4;
}

// ============================================================================
extern "C" void kernel_launch(void* const* d_in, const int* in_sizes, int n_in,
                              void* d_out, int out_size) {
    (void)in_sizes; (void)n_in; (void)out_size;
    const float* x     = (const float*)d_in[0];
    const float* plast = (const float*)d_in[1];
    const float* alpha = (const float*)d_in[2];
    const float* Wslow = (const float*)d_in[3];
    const float* Wfast = (const float*)d_in[4];
    const float* gamma = (const float*)d_in[5];
    const float* beta  = (const float*)d_in[6];

    float* out  = (float*)d_out;                 // [16384, 1024]
    float* slow = out  + (size_t)BATCH * D;      // [16384, 1024]
    float* wnew = slow + (size_t)BATCH * D;      // [1024, 1024]

    gemm_xw<<<dim3(8, 128), 256>>>(x, Wslow, slow);     // slow
    gemm_xw<<<dim3(8, 128), 256>>>(x, Wfast, nullptr);  // fast -> g_fast
    msq_stageA<<<dim3(4, 64), 256>>>();
    msq_stageB<<<4, 256>>>();
    efflr_kernel<<<1, 256>>>(plast);
    gemm_atb<<<dim3(8, 8, 8), 256>>>(x);                // fast^T @ x partials
    finalize_w<<<1024, 256>>>(Wfast, wnew);
    ln_kernel<<<16384, 256>>>(slow, alpha, gamma, beta, out);
}

// round 6
// speedup vs baseline: 2.0267x; 2.0267x over previous
#include <cuda_runtime.h>
#include <cstdint>

#define BATCH 16384
#define D     1024
#define LN_EPS 1e-5f

// ---------------- scratch (static device globals; no runtime alloc) ----------
__device__ __align__(16) float g_xc   [(size_t)BATCH * D];  // x rounded to tf32
__device__ __align__(16) float g_wsc  [(size_t)D * D];      // W_slow rounded
__device__ __align__(16) float g_wfc  [(size_t)D * D];      // W_fast rounded
__device__ __align__(16) float g_fast [(size_t)BATCH * D];  // fast, fp32
__device__ __align__(16) float g_fastc[(size_t)BATCH * D];  // fast, tf32-rounded
__device__ __align__(16) float g_part [(size_t)8 * D * D];  // split-K partials
__device__ float g_msq_part[64 * D];
__device__ float g_msq[D];
__device__ float g_efflr[1];

// ---------------- helpers ----------------------------------------------------
__device__ __forceinline__ unsigned tf32u(float x) {
    unsigned r;
    asm("cvt.rna.tf32.f32 %0, %1;" : "=r"(r) : "f"(x));
    return r;
}
__device__ __forceinline__ unsigned fu(float x) { return __float_as_uint(x); }

__device__ __forceinline__ void mma8(float c[4],
                                     unsigned a0, unsigned a1, unsigned a2, unsigned a3,
                                     unsigned b0, unsigned b1) {
    asm volatile(
        "mma.sync.aligned.m16n8k8.row.col.f32.tf32.tf32.f32 "
        "{%0,%1,%2,%3}, {%4,%5,%6,%7}, {%8,%9}, {%0,%1,%2,%3};\n"
        : "+f"(c[0]), "+f"(c[1]), "+f"(c[2]), "+f"(c[3])
        : "r"(a0), "r"(a1), "r"(a2), "r"(a3), "r"(b0), "r"(b1));
}

__device__ __forceinline__ void cpa16(void* dst, const void* src) {
    unsigned sd = (unsigned)__cvta_generic_to_shared(dst);
    asm volatile("cp.async.cg.shared.global [%0], [%1], 16;\n" :: "r"(sd), "l"(src));
}
#define CP_COMMIT() asm volatile("cp.async.commit_group;\n" ::: "memory")
#define CP_WAIT1()  asm volatile("cp.async.wait_group 1;\n" ::: "memory")
#define CP_WAIT0()  asm volatile("cp.async.wait_group 0;\n" ::: "memory")

__device__ __forceinline__ float warpSum(float v) {
    #pragma unroll
    for (int o = 16; o > 0; o >>= 1) v += __shfl_xor_sync(0xffffffffu, v, o);
    return v;
}

// ============================================================================
// Pre-convert: round fp32 -> tf32 (rna) once, in gmem
// ============================================================================
__global__ void cvt_rna_kernel(const float4* __restrict__ s, float4* __restrict__ d, int n4) {
    int i  = blockIdx.x * 256 + threadIdx.x;
    int st = gridDim.x * 256;
    for (; i < n4; i += st) {
        float4 v = s[i];
        v.x = __uint_as_float(tf32u(v.x));
        v.y = __uint_as_float(tf32u(v.y));
        v.z = __uint_as_float(tf32u(v.z));
        v.w = __uint_as_float(tf32u(v.w));
        d[i] = v;
    }
}

// ============================================================================
// GEMM 1: C[m][n] = sum_k xc[m][k] * Wc[n][k]
// 128x128 block tile, 4 warps (2x2 of 64x64), BK=16, cp.async double buffer.
// mode 0: W=g_wsc, write C.   mode 1: W=g_wfc, write g_fast + g_fastc.
// ============================================================================
__global__ __launch_bounds__(128)
void gemm_xw(float* __restrict__ C, int mode) {
    __shared__ float As[2][128][20];
    __shared__ float Bs[2][128][20];
    const int K = D;

    const int tid  = threadIdx.x;
    const int warp = tid >> 5, lane = tid & 31;
    const int g = lane >> 2, tg = lane & 3;
    const int wm = (warp >> 1) * 64;
    const int wn = (warp & 1) * 64;

    const float* __restrict__ Ab = g_xc + (size_t)blockIdx.y * 128 * K;
    const float* __restrict__ Wb = (mode ? (const float*)g_wfc : (const float*)g_wsc)
                                   + (size_t)blockIdx.x * 128 * K;

    float acc[4][8][4];
    #pragma unroll
    for (int i = 0; i < 4; i++)
        #pragma unroll
        for (int j = 0; j < 8; j++)
            #pragma unroll
            for (int q = 0; q < 4; q++) acc[i][j][q] = 0.f;

    const int lr = tid >> 2;          // 0..31
    const int lc = (tid & 3) << 2;    // 0,4,8,12

    auto LOAD = [&](int s, int k0) {
        #pragma unroll
        for (int i = 0; i < 4; i++) {
            int r = lr + i * 32;
            cpa16(&As[s][r][lc], Ab + (size_t)r * K + k0 + lc);
            cpa16(&Bs[s][r][lc], Wb + (size_t)r * K + k0 + lc);
        }
    };

    auto COMP = [&](int s) {
        #pragma unroll
        for (int ks = 0; ks < 2; ks++) {
            const int kk = ks * 8;
            unsigned a[4][4], b[8][2];
            #pragma unroll
            for (int im = 0; im < 4; im++) {
                int m = wm + im * 16;
                a[im][0] = fu(As[s][m + g    ][kk + tg    ]);
                a[im][1] = fu(As[s][m + g + 8][kk + tg    ]);
                a[im][2] = fu(As[s][m + g    ][kk + tg + 4]);
                a[im][3] = fu(As[s][m + g + 8][kk + tg + 4]);
            }
            #pragma unroll
            for (int jn = 0; jn < 8; jn++) {
                int n = wn + jn * 8;
                b[jn][0] = fu(Bs[s][n + g][kk + tg    ]);
                b[jn][1] = fu(Bs[s][n + g][kk + tg + 4]);
            }
            #pragma unroll
            for (int im = 0; im < 4; im++)
                #pragma unroll
                for (int jn = 0; jn < 8; jn++)
                    mma8(acc[im][jn], a[im][0], a[im][1], a[im][2], a[im][3],
                         b[jn][0], b[jn][1]);
        }
    };

    LOAD(0, 0); CP_COMMIT();
    const int NK = K / 16;  // 64
    for (int it = 0; it < NK; it++) {
        if (it + 1 < NK) { LOAD((it + 1) & 1, (it + 1) * 16); CP_COMMIT(); CP_WAIT1(); }
        else             { CP_WAIT0(); }
        __syncthreads();
        COMP(it & 1);
        __syncthreads();
    }

    float* Cf = mode ? (float*)g_fast : C;
    #pragma unroll
    for (int im = 0; im < 4; im++) {
        int m = blockIdx.y * 128 + wm + im * 16 + g;
        #pragma unroll
        for (int jn = 0; jn < 8; jn++) {
            int n = blockIdx.x * 128 + wn + jn * 8 + tg * 2;
            float2 v0 = make_float2(acc[im][jn][0], acc[im][jn][1]);
            float2 v1 = make_float2(acc[im][jn][2], acc[im][jn][3]);
            *(float2*)(Cf + (size_t)m * D + n)       = v0;
            *(float2*)(Cf + (size_t)(m + 8) * D + n) = v1;
            if (mode) {
                float2 r0 = make_float2(__uint_as_float(tf32u(v0.x)), __uint_as_float(tf32u(v0.y)));
                float2 r1 = make_float2(__uint_as_float(tf32u(v1.x)), __uint_as_float(tf32u(v1.y)));
                *(float2*)((float*)g_fastc + (size_t)m * D + n)       = r0;
                *(float2*)((float*)g_fastc + (size_t)(m + 8) * D + n) = r1;
            }
        }
    }
}

// ============================================================================
// GEMM 2 (split-K): partial[z][m][n] = sum_{k chunk z} fastc[k][m] * xc[k][n]
// 128x128 block tile, 4 warps (2x2 of 64x64), BK=16, cp.async double buffer.
// grid (8 ntiles, 8 mtiles, 8 splits)
// ============================================================================
__global__ __launch_bounds__(128)
void gemm_atb() {
    __shared__ float As[2][16][136];
    __shared__ float Bs[2][16][136];

    const int tid  = threadIdx.x;
    const int warp = tid >> 5, lane = tid & 31;
    const int g = lane >> 2, tg = lane & 3;
    const int wm = (warp >> 1) * 64;
    const int wn = (warp & 1) * 64;
    const int m0 = blockIdx.y * 128, n0 = blockIdx.x * 128;
    const int kbase = blockIdx.z * (BATCH / 8);   // 2048 per split

    float acc[4][8][4];
    #pragma unroll
    for (int i = 0; i < 4; i++)
        #pragma unroll
        for (int j = 0; j < 8; j++)
            #pragma unroll
            for (int q = 0; q < 4; q++) acc[i][j][q] = 0.f;

    const int lr = tid >> 3;          // 0..15
    const int lc = (tid & 7) << 2;    // 0..28

    auto LOAD = [&](int s, int k0) {
        #pragma unroll
        for (int i = 0; i < 4; i++) {
            int c = lc + 32 * i;
            cpa16(&As[s][lr][c], (const float*)g_fastc + (size_t)(k0 + lr) * D + m0 + c);
            cpa16(&Bs[s][lr][c], (const float*)g_xc    + (size_t)(k0 + lr) * D + n0 + c);
        }
    };

    auto COMP = [&](int s) {
        #pragma unroll
        for (int ks = 0; ks < 2; ks++) {
            const int kk = ks * 8;
            unsigned a[4][4], b[8][2];
            #pragma unroll
            for (int im = 0; im < 4; im++) {
                int m = wm + im * 16;
                a[im][0] = fu(As[s][kk + tg    ][m + g    ]);
                a[im][1] = fu(As[s][kk + tg    ][m + g + 8]);
                a[im][2] = fu(As[s][kk + tg + 4][m + g    ]);
                a[im][3] = fu(As[s][kk + tg + 4][m + g + 8]);
            }
            #pragma unroll
            for (int jn = 0; jn < 8; jn++) {
                int n = wn + jn * 8;
                b[jn][0] = fu(Bs[s][kk + tg    ][n + g]);
                b[jn][1] = fu(Bs[s][kk + tg + 4][n + g]);
            }
            #pragma unroll
            for (int im = 0; im < 4; im++)
                #pragma unroll
                for (int jn = 0; jn < 8; jn++)
                    mma8(acc[im][jn], a[im][0], a[im][1], a[im][2], a[im][3],
                         b[jn][0], b[jn][1]);
        }
    };

    LOAD(0, kbase); CP_COMMIT();
    const int NK = (BATCH / 8) / 16;  // 128
    for (int it = 0; it < NK; it++) {
        if (it + 1 < NK) { LOAD((it + 1) & 1, kbase + (it + 1) * 16); CP_COMMIT(); CP_WAIT1(); }
        else             { CP_WAIT0(); }
        __syncthreads();
        COMP(it & 1);
        __syncthreads();
    }

    float* Cp = (float*)g_part + (size_t)blockIdx.z * D * D;
    #pragma unroll
    for (int im = 0; im < 4; im++) {
        int m = m0 + wm + im * 16 + g;
        #pragma unroll
        for (int jn = 0; jn < 8; jn++) {
            int n = n0 + wn + jn * 8 + tg * 2;
            *(float2*)(Cp + (size_t)m * D + n)       = make_float2(acc[im][jn][0], acc[im][jn][1]);
            *(float2*)(Cp + (size_t)(m + 8) * D + n) = make_float2(acc[im][jn][2], acc[im][jn][3]);
        }
    }
}

// ============================================================================
// mean(fast^2, axis=0): two deterministic stages
// ============================================================================
__global__ void msq_stageA() {
    int c  = blockIdx.x * 256 + threadIdx.x;     // grid.x = 4
    int r0 = blockIdx.y * 256;                   // grid.y = 64
    float s0 = 0.f, s1 = 0.f, s2 = 0.f, s3 = 0.f;
    const float* fp = (const float*)g_fast + (size_t)r0 * D + c;
    #pragma unroll 4
    for (int j = 0; j < 256; j += 4) {
        float v0 = fp[(size_t)(j + 0) * D];
        float v1 = fp[(size_t)(j + 1) * D];
        float v2 = fp[(size_t)(j + 2) * D];
        float v3 = fp[(size_t)(j + 3) * D];
        s0 += v0 * v0; s1 += v1 * v1; s2 += v2 * v2; s3 += v3 * v3;
    }
    g_msq_part[blockIdx.y * D + c] = (s0 + s1) + (s2 + s3);
}

__global__ void msq_stageB() {
    int c = blockIdx.x * 256 + threadIdx.x;      // grid.x = 4
    float s = 0.f;
    #pragma unroll
    for (int j = 0; j < 64; j++) s += g_msq_part[j * D + c];
    g_msq[c] = s * (1.0f / (float)BATCH);
}

// ============================================================================
// eff_lr = mean(plasticity) * 0.1
// ============================================================================
__global__ void efflr_kernel(const float* __restrict__ p) {
    int t = threadIdx.x;
    float s = 0.f;
    for (int j = t; j < BATCH; j += 256) s += p[j];
    s = warpSum(s);
    __shared__ float sh[8];
    if ((t & 31) == 0) sh[t >> 5] = s;
    __syncthreads();
    if (t == 0) {
        float tot = 0.f;
        #pragma unroll
        for (int i = 0; i < 8; i++) tot += sh[i];
        g_efflr[0] = tot * (0.1f / (float)BATCH);
    }
}

// ============================================================================
// W_fast_new = W_fast + tanh(hebb - msq[o]*W_fast) * eff_lr
// ============================================================================
__global__ __launch_bounds__(256)
void finalize_w(const float* __restrict__ Wf, float* __restrict__ wnew) {
    int o = blockIdx.x;
    float msq = g_msq[o];
    float lr  = g_efflr[0];
    for (int j = threadIdx.x; j < D; j += 256) {
        size_t i = (size_t)o * D + j;
        float h = 0.f;
        #pragma unroll
        for (int s = 0; s < 8; s++) h += g_part[(size_t)s * D * D + i];
        float wf = Wf[i];
        wnew[i] = wf + tanhf(h * (1.0f / (float)BATCH) - msq * wf) * lr;
    }
}

// ============================================================================
// LayerNorm over combined = slow + alpha*fast; one block per row
// ============================================================================
__global__ __launch_bounds__(256)
void ln_kernel(const float* __restrict__ slow, const float* __restrict__ alpha,
               const float* __restrict__ gamma, const float* __restrict__ beta,
               float* __restrict__ out) {
    int r = blockIdx.x, t = threadIdx.x;
    const float a = alpha[0];
    float4 s4 = ((const float4*)(slow + (size_t)r * D))[t];
    float4 f4 = ((const float4*)((const float*)g_fast + (size_t)r * D))[t];
    float4 v;
    v.x = s4.x + a * f4.x; v.y = s4.y + a * f4.y;
    v.z = s4.z + a * f4.z; v.w = s4.w + a * f4.w;

    float sum = (v.x + v.y) + (v.z + v.w);
    float sq  = (v.x * v.x + v.y * v.y) + (v.z * v.z + v.w * v.w);
    sum = warpSum(sum); sq = warpSum(sq);

    __shared__ float sh[16];
    int w = t >> 5, l = t & 31;
    if (l == 0) { sh[w] = sum; sh[8 + w] = sq; }
    __syncthreads();
    if (t == 0) {
        float s = 0.f, q = 0.f;
        #pragma unroll
        for (int i = 0; i < 8; i++) { s += sh[i]; q += sh[8 + i]; }
        sh[0] = s; sh[8] = q;
    }
    __syncthreads();
    float mu  = sh[0] * (1.0f / (float)D);
    float var = sh[8] * (1.0f / (float)D) - mu * mu;
    float rs  = rsqrtf(var + LN_EPS);

    float4 g4 = ((const float4*)gamma)[t];
    float4 b4 = ((const float4*)beta)[t];
    float4 o4;
    o4.x = (v.x - mu) * rs * g4.x + b4.x;
    o4.y = (v.y - mu) * rs * g4.y + b4.y;
    o4.z = (v.z - mu) * rs * g4.z + b4.z;
    o4.w = (v.w - mu) * rs * g4.w + b4.w;
    ((float4*)(out + (size_t)r * D))[t] = o4;
}

// ============================================================================
extern "C" void kernel_launch(void* const* d_in, const int* in_sizes, int n_in,
                              void* d_out, int out_size) {
    (void)in_sizes; (void)n_in; (void)out_size;
    const float* x     = (const float*)d_in[0];
    const float* plast = (const float*)d_in[1];
    const float* alpha = (const float*)d_in[2];
    const float* Wslow = (const float*)d_in[3];
    const float* Wfast = (const float*)d_in[4];
    const float* gamma = (const float*)d_in[5];
    const float* beta  = (const float*)d_in[6];

    float* out  = (float*)d_out;                 // [16384, 1024]
    float* slow = out  + (size_t)BATCH * D;      // [16384, 1024]
    float* wnew = slow + (size_t)BATCH * D;      // [1024, 1024]

    // symbol addresses resolved device-side; host passes only selectors/harness ptrs
    float* d_xc  = nullptr; cudaGetSymbolAddress((void**)&d_xc,  g_xc);
    float* d_wsc = nullptr; cudaGetSymbolAddress((void**)&d_wsc, g_wsc);
    float* d_wfc = nullptr; cudaGetSymbolAddress((void**)&d_wfc, g_wfc);

    cvt_rna_kernel<<<1024, 256>>>((const float4*)x,     (float4*)d_xc,  BATCH * D / 4);
    cvt_rna_kernel<<<256,  256>>>((const float4*)Wslow, (float4*)d_wsc, D * D / 4);
    cvt_rna_kernel<<<256,  256>>>((const float4*)Wfast, (float4*)d_wfc, D * D / 4);

    gemm_xw<<<dim3(8, 128), 128>>>(slow, 0);        // slow = x @ Wslow^T
    gemm_xw<<<dim3(8, 128), 128>>>(nullptr, 1);     // fast -> g_fast + g_fastc

    msq_stageA<<<dim3(4, 64), 256>>>();
    msq_stageB<<<4, 256>>>();
    efflr_kernel<<<1, 256>>>(plast);

    gemm_atb<<<dim3(8, 8, 8), 128>>>();             // fast^T @ x partials

    finalize_w<<<1024, 256>>>(Wfast, wnew);
    ln_kernel<<<16384, 256>>>(slow, alpha, gamma, beta, out);
}